// round 14
// baseline (speedup 1.0000x reference)
#include <cuda_runtime.h>
#include <cuda_bf16.h>
#include <cuda_fp16.h>
#include <math.h>
#include <stdint.h>

// ---------------------------------------------------------------------------
// Problem constants
// ---------------------------------------------------------------------------
#define BB    2
#define TT    64
#define PP    256
#define DD    512
#define HH    8
#define DH    64
#define INNER 512          // HH*DH
#define QKV3  1536         // 3*INNER
#define NTOK  32768        // BB*TT*PP
#define DEPTH 4
#define LN_EPS 1e-5f

#define WQKV_SZ (DEPTH * DD * QKV3)
#define WOUT_SZ (DEPTH * INNER * DD)

// ---------------------------------------------------------------------------
// Static device scratch (qkv/ctx/xs/xt fp16; x residual stays fp32)
// g_ctx doubles as the LN-output buffer (lifetimes disjoint).
// ---------------------------------------------------------------------------
__device__ __half   g_qkv[(size_t)NTOK * QKV3];
__device__ __half   g_ctx[(size_t)NTOK * INNER];
__device__ __half   g_xs [(size_t)NTOK * DD];
__device__ __half   g_xt [(size_t)NTOK * DD];
__device__ uint32_t g_wp [WQKV_SZ + WOUT_SZ];   // k-pair-packed fp16 weights
__device__ float    g_cos[256 * 32];
__device__ float    g_sin[256 * 32];

// ---------------------------------------------------------------------------
// RoPE table
// ---------------------------------------------------------------------------
__global__ void rope_table_kernel() {
    int i = blockIdx.x * blockDim.x + threadIdx.x;
    if (i >= 256 * 32) return;
    int pos = i >> 5;
    int j   = i & 31;
    float freq  = powf(10000.0f, -(float)(2 * j) / 64.0f);
    float theta = (float)pos * freq;
    float s, c;
    sincosf(theta, &s, &c);
    g_cos[i] = c;
    g_sin[i] = s;
}

// ---------------------------------------------------------------------------
// Fast exp on the FMA pipe
// ---------------------------------------------------------------------------
__device__ __forceinline__ float fexp(float x) {
    x = fmaxf(x, -80.0f);
    float y = x * 1.44269504088896340736f;
    float t = y + 12582912.0f;
    int   n = __float_as_int(t) - 0x4B400000;
    float f = y - (t - 12582912.0f);
    float p =             1.54035303933e-4f;
    p = fmaf(p, f, 1.33335581464e-3f);
    p = fmaf(p, f, 9.61812910763e-3f);
    p = fmaf(p, f, 5.55041086648e-2f);
    p = fmaf(p, f, 2.40226506959e-1f);
    p = fmaf(p, f, 6.93147180560e-1f);
    p = fmaf(p, f, 1.0f);
    return p * __int_as_float((n + 127) << 23);
}

__device__ __forceinline__ void mma_f16(float c[4],
                                        uint32_t a0, uint32_t a1, uint32_t a2, uint32_t a3,
                                        uint32_t b0, uint32_t b1)
{
    asm volatile(
        "mma.sync.aligned.m16n8k16.row.col.f32.f16.f16.f32 "
        "{%0,%1,%2,%3}, {%4,%5,%6,%7}, {%8,%9}, {%0,%1,%2,%3};"
        : "+f"(c[0]), "+f"(c[1]), "+f"(c[2]), "+f"(c[3])
        : "r"(a0), "r"(a1), "r"(a2), "r"(a3), "r"(b0), "r"(b1));
}

__device__ __forceinline__ void cp_async16(uint32_t dst, const void* src) {
    asm volatile("cp.async.cg.shared.global [%0], [%1], 16;\n" :: "r"(dst), "l"(src));
}

// ---------------------------------------------------------------------------
// Fused weight prep: all 4 groups x 4 layers in one launch.
// blockIdx.z = group (0=qkv_s, 1=out_s, 2=qkv_t, 3=out_t), blockIdx.y = layer.
// ---------------------------------------------------------------------------
__global__ void pack_all_kernel(const float* __restrict__ wq_s,
                                const float* __restrict__ wo_s,
                                const float* __restrict__ wq_t,
                                const float* __restrict__ wo_t,
                                uint32_t* __restrict__ dst_base)
{
    int grpi = blockIdx.z;
    int z    = blockIdx.y;
    int K2 = (grpi & 1) ? (INNER / 2) : (DD / 2);
    int N  = (grpi & 1) ? DD : QKV3;
    int i = blockIdx.x * blockDim.x + threadIdx.x;
    if (i >= K2 * N) return;
    const float* src = (grpi == 0) ? wq_s : (grpi == 1) ? wo_s : (grpi == 2) ? wq_t : wo_t;
    size_t dsto = (grpi == 0) ? 0
                : (grpi == 1) ? (size_t)WQKV_SZ / 2
                : (grpi == 2) ? (size_t)(WQKV_SZ + WOUT_SZ) / 2
                :               (size_t)WQKV_SZ + WOUT_SZ / 2;
    const float* s = src + (size_t)z * 2 * K2 * N;
    int k2 = i / N, n = i - k2 * N;
    __half2 h = __floats2half2_rn(s[(size_t)(2 * k2) * N + n],
                                  s[(size_t)(2 * k2 + 1) * N + n]);
    dst_base[dsto + (size_t)z * K2 * N + i] = *(uint32_t*)&h;
}

// ---------------------------------------------------------------------------
// Warp-per-row LayerNorm over D=512
// ---------------------------------------------------------------------------
__device__ __forceinline__ void warp_ln_core(
    const float4 v[4], int lane,
    const float* __restrict__ g, const float* __restrict__ b,
    float4 o[4])
{
    float s = 0.f, s2 = 0.f;
#pragma unroll
    for (int i = 0; i < 4; i++) {
        s  += v[i].x + v[i].y + v[i].z + v[i].w;
        s2 += v[i].x * v[i].x + v[i].y * v[i].y + v[i].z * v[i].z + v[i].w * v[i].w;
    }
#pragma unroll
    for (int o_ = 16; o_ > 0; o_ >>= 1) {
        s  += __shfl_xor_sync(0xffffffffu, s,  o_);
        s2 += __shfl_xor_sync(0xffffffffu, s2, o_);
    }
    float mu   = s * (1.0f / 512.0f);
    float var  = s2 * (1.0f / 512.0f) - mu * mu;
    float rstd = rsqrtf(var + LN_EPS);
#pragma unroll
    for (int i = 0; i < 4; i++) {
        int c = (lane + 32 * i) * 4;
        float4 gg = *(const float4*)(g + c);
        float4 bb = *(const float4*)(b + c);
        o[i].x = (v[i].x - mu) * rstd * gg.x + bb.x;
        o[i].y = (v[i].y - mu) * rstd * gg.y + bb.y;
        o[i].z = (v[i].z - mu) * rstd * gg.z + bb.z;
        o[i].w = (v[i].w - mu) * rstd * gg.w + bb.w;
    }
}

__device__ __forceinline__ void store_half4(__half* p, float4 o) {
    __half2 ha = __floats2half2_rn(o.x, o.y);
    __half2 hb = __floats2half2_rn(o.z, o.w);
    uint2 pk = make_uint2(*(uint32_t*)&ha, *(uint32_t*)&hb);
    *(uint2*)p = pk;
}

__device__ __forceinline__ float4 load_half4(const __half* p) {
    uint2 pk = *(const uint2*)p;
    __half2 ha = *(__half2*)&pk.x;
    __half2 hb = *(__half2*)&pk.y;
    return make_float4(__half2float(__low2half(ha)), __half2float(__high2half(ha)),
                       __half2float(__low2half(hb)), __half2float(__high2half(hb)));
}

// out = fp16(LN(x))
__global__ void ln_kernel(const float* __restrict__ x,
                          const float* __restrict__ g, const float* __restrict__ b,
                          __half* __restrict__ out)
{
    int row  = blockIdx.x * 8 + (threadIdx.x >> 5);
    int lane = threadIdx.x & 31;
    const float* xr = x + (size_t)row * DD;
    float4 v[4];
#pragma unroll
    for (int i = 0; i < 4; i++) v[i] = *(const float4*)(xr + (lane + 32 * i) * 4);
    float4 o[4];
    warp_ln_core(v, lane, g, b, o);
    __half* orow = out + (size_t)row * DD;
#pragma unroll
    for (int i = 0; i < 4; i++) store_half4(orow + (lane + 32 * i) * 4, o[i]);
}

// out = fp16(LN(x[src] + xs[src])) in (b,p,t) order
__global__ void ln_add_transpose_kernel(const float* __restrict__ x,
                                        const __half* __restrict__ xs,
                                        const float* __restrict__ g, const float* __restrict__ b,
                                        __half* __restrict__ out)
{
    int row  = blockIdx.x * 8 + (threadIdx.x >> 5);
    int lane = threadIdx.x & 31;
    int t_ = row & 63;
    int p_ = (row >> 6) & 255;
    int b_ = row >> 14;
    int src = (b_ * TT + t_) * PP + p_;
    const float* xr   = x  + (size_t)src * DD;
    const __half* xsr = xs + (size_t)src * DD;
    float4 v[4];
#pragma unroll
    for (int i = 0; i < 4; i++) {
        float4 a = *(const float4*)(xr + (lane + 32 * i) * 4);
        float4 c = load_half4(xsr + (lane + 32 * i) * 4);
        v[i].x = a.x + c.x; v[i].y = a.y + c.y; v[i].z = a.z + c.z; v[i].w = a.w + c.w;
    }
    float4 o[4];
    warp_ln_core(v, lane, g, b, o);
    __half* orow = out + (size_t)row * DD;
#pragma unroll
    for (int i = 0; i < 4; i++) store_half4(orow + (lane + 32 * i) * 4, o[i]);
}

// x = LN(xs + xt[perm]) + x
__global__ void ln_final_kernel(const __half* __restrict__ xs,
                                const __half* __restrict__ xt,
                                const float* __restrict__ g, const float* __restrict__ b,
                                float* __restrict__ x)
{
    int row  = blockIdx.x * 8 + (threadIdx.x >> 5);
    int lane = threadIdx.x & 31;
    int p_ = row & 255;
    int t_ = (row >> 8) & 63;
    int b_ = row >> 14;
    int xtr = (b_ * PP + p_) * TT + t_;
    const __half* xsr   = xs + (size_t)row * DD;
    const __half* xtr_p = xt + (size_t)xtr * DD;
    float* xr = x + (size_t)row * DD;
    float4 v[4], xv[4];
#pragma unroll
    for (int i = 0; i < 4; i++) {
        float4 a = load_half4(xsr   + (lane + 32 * i) * 4);
        float4 c = load_half4(xtr_p + (lane + 32 * i) * 4);
        v[i].x = a.x + c.x; v[i].y = a.y + c.y; v[i].z = a.z + c.z; v[i].w = a.w + c.w;
        xv[i] = *(const float4*)(xr + (lane + 32 * i) * 4);
    }
    float4 o[4];
    warp_ln_core(v, lane, g, b, o);
#pragma unroll
    for (int i = 0; i < 4; i++) {
        o[i].x += xv[i].x; o[i].y += xv[i].y; o[i].z += xv[i].z; o[i].w += xv[i].w;
        *(float4*)(xr + (lane + 32 * i) * 4) = o[i];
    }
}

// ---------------------------------------------------------------------------
// fp16 tensor-core GEMM, fp16 output, 128x128x64 tile (unchanged from R13)
// ---------------------------------------------------------------------------
#define HA_STR 72
#define HB_STR 136
#define HA_BUF (128 * HA_STR)
#define HB_BUF (32 * HB_STR)
#define HGEMM_SMEM (2 * HA_BUF * 2 + 2 * HB_BUF * 4)

__global__ void __launch_bounds__(256, 2) hgemm_kernel(
    const __half* __restrict__ A, const uint32_t* __restrict__ Bp,
    const float* __restrict__ bias, __half* __restrict__ C,
    int M, int N, int K)
{
    extern __shared__ char smem[];
    __half*   As = (__half*)smem;
    uint32_t* Bs = (uint32_t*)(smem + 2 * HA_BUF * 2);

    int tid  = threadIdx.x;
    int lane = tid & 31;
    int wid  = tid >> 5;
    int wm   = wid >> 2;
    int wn   = wid & 3;
    int grp  = lane >> 2;
    int tig  = lane & 3;
    int bm = blockIdx.x, bn = blockIdx.y;

    const __half*   Ag = A  + (size_t)bm * 128 * K;
    const uint32_t* Bg = Bp + bn * 128;

    uint32_t as_base = (uint32_t)__cvta_generic_to_shared(As);
    uint32_t bs_base = (uint32_t)__cvta_generic_to_shared(Bs);

    float acc[4][4][4];
#pragma unroll
    for (int i = 0; i < 4; i++)
#pragma unroll
        for (int j = 0; j < 4; j++)
#pragma unroll
            for (int c = 0; c < 4; c++) acc[i][j][c] = 0.f;

    const int NK = K / 64;

    auto load_tiles = [&](int kt, int buf) {
#pragma unroll
        for (int it = 0; it < 4; it++) {
            int slot = tid + it * 256;
            int row  = slot >> 3;
            int seg  = slot & 7;
            uint32_t dst = as_base + buf * (HA_BUF * 2) + row * (HA_STR * 2) + seg * 16;
            cp_async16(dst, Ag + (size_t)row * K + kt * 64 + seg * 8);
        }
#pragma unroll
        for (int it = 0; it < 4; it++) {
            int slot = tid + it * 256;
            int row  = slot >> 5;
            int seg  = slot & 31;
            uint32_t dst = bs_base + buf * (HB_BUF * 4) + row * (HB_STR * 4) + seg * 16;
            cp_async16(dst, Bg + (size_t)(kt * 32 + row) * N + seg * 4);
        }
        asm volatile("cp.async.commit_group;\n");
    };

    load_tiles(0, 0);

    for (int kt = 0; kt < NK; kt++) {
        int buf = kt & 1;
        if (kt + 1 < NK) {
            load_tiles(kt + 1, buf ^ 1);
            asm volatile("cp.async.wait_group 1;\n");
        } else {
            asm volatile("cp.async.wait_group 0;\n");
        }
        __syncthreads();

        const __half*   as = As + buf * HA_BUF;
        const uint32_t* bs = Bs + buf * HB_BUF;

#pragma unroll
        for (int ks = 0; ks < 4; ks++) {
            uint32_t af[4][4];
#pragma unroll
            for (int mt = 0; mt < 4; mt++) {
                int m = wm * 64 + mt * 16;
                const __half* ar0 = &as[(m + grp    ) * HA_STR + ks * 16 + 2 * tig];
                const __half* ar1 = &as[(m + grp + 8) * HA_STR + ks * 16 + 2 * tig];
                af[mt][0] = *(const uint32_t*)ar0;
                af[mt][1] = *(const uint32_t*)ar1;
                af[mt][2] = *(const uint32_t*)(ar0 + 8);
                af[mt][3] = *(const uint32_t*)(ar1 + 8);
            }
            uint32_t bf[4][2];
#pragma unroll
            for (int nt = 0; nt < 4; nt++) {
                int n = wn * 32 + nt * 8;
                bf[nt][0] = bs[(ks * 8 + tig    ) * HB_STR + n + grp];
                bf[nt][1] = bs[(ks * 8 + tig + 4) * HB_STR + n + grp];
            }
#pragma unroll
            for (int mt = 0; mt < 4; mt++)
#pragma unroll
                for (int nt = 0; nt < 4; nt++)
                    mma_f16(acc[mt][nt], af[mt][0], af[mt][1], af[mt][2], af[mt][3],
                            bf[nt][0], bf[nt][1]);
        }
        __syncthreads();
    }

#pragma unroll
    for (int nt = 0; nt < 4; nt++) {
        int colg = bn * 128 + wn * 32 + nt * 8 + 2 * tig;
        float2 bv = {0.f, 0.f};
        if (bias) bv = *(const float2*)(bias + colg);
#pragma unroll
        for (int mt = 0; mt < 4; mt++) {
            int row0 = bm * 128 + wm * 64 + mt * 16 + grp;
            *(__half2*)(C + (size_t)row0 * N + colg) =
                __floats2half2_rn(acc[mt][nt][0] + bv.x, acc[mt][nt][1] + bv.y);
            *(__half2*)(C + (size_t)(row0 + 8) * N + colg) =
                __floats2half2_rn(acc[mt][nt][2] + bv.x, acc[mt][nt][3] + bv.y);
        }
    }
}

// ---------------------------------------------------------------------------
// fp16 tensor-core flash attention. Warp count from blockDim:
// block handles QT = (blockDim/32)*16 queries; warp w owns 16 q-rows.
// Spatial: 256 threads -> 128 queries/CTA (KV staged once per 128 queries).
// Temporal: 128 threads -> 64 queries/CTA.
// ---------------------------------------------------------------------------
#define ASTH 72                 // halves per tile row

__global__ void __launch_bounds__(256, 2) attn_tc_kernel(
    const __half* __restrict__ qkv, __half* __restrict__ ctx, int L)
{
    __shared__ __half qs [128 * ASTH];   // sized for max QT; doubles as ps
    __shared__ __half ks [64 * ASTH];
    __shared__ __half vsT[64 * ASTH];
    __half* ps = qs;

    int nthr = blockDim.x;
    int tid  = threadIdx.x;
    int lane = tid & 31;
    int w    = tid >> 5;
    int grp  = lane >> 2;
    int tig  = lane & 3;
    int QT   = (nthr >> 5) << 4;         // queries per block
    int qt = blockIdx.x, h = blockIdx.y;
    size_t seq_base = (size_t)blockIdx.z * L;
    int qbase = qt * QT;
    int m0 = w * 16;

    // ---- stage Q (rotary + scale -> fp16), QT*32 pairs ----
    for (int slot = tid; slot < (QT << 5); slot += nthr) {
        int row = slot >> 5, pr = slot & 31;
        int pos = qbase + row;
        const __half* p = qkv + (seq_base + pos) * QKV3 + h * DH + 2 * pr;
        __half2 qh = *(const __half2*)p;
        float qx = __half2float(__low2half(qh)), qy = __half2float(__high2half(qh));
        float c = g_cos[pos * 32 + pr], sn = g_sin[pos * 32 + pr];
        float e0 = (qx * c - qy * sn) * 0.125f;
        float e1 = (qy * c + qx * sn) * 0.125f;
        *(__half2*)&qs[row * ASTH + 2 * pr] = __floats2half2_rn(e0, e1);
    }

    auto stage_kv = [&](int kt) {
        for (int slot = tid; slot < 2048; slot += nthr) {
            int row = slot >> 5, pr = slot & 31;
            int pos = kt * 64 + row;
            const __half* p = qkv + (seq_base + pos) * QKV3 + INNER + h * DH + 2 * pr;
            __half2 kh = *(const __half2*)p;
            float kx = __half2float(__low2half(kh)), ky = __half2float(__high2half(kh));
            float c = g_cos[pos * 32 + pr], sn = g_sin[pos * 32 + pr];
            float e0 = kx * c - ky * sn;
            float e1 = ky * c + kx * sn;
            *(__half2*)&ks[row * ASTH + 2 * pr] = __floats2half2_rn(e0, e1);
        }
        for (int slot = tid; slot < 2048; slot += nthr) {
            int d  = slot & 63;
            int pp = slot >> 6;
            const __half* p = qkv + (seq_base + kt * 64 + 2 * pp) * QKV3
                            + 2 * INNER + h * DH + d;
            __half v0 = p[0];
            __half v1 = p[QKV3];
            *(__half2*)&vsT[d * ASTH + 2 * pp] = __halves2half2(v0, v1);
        }
    };

    stage_kv(0);
    __syncthreads();

    uint32_t qa[4][4];
#pragma unroll
    for (int kk = 0; kk < 4; kk++) {
        const uint32_t* r0 = (const uint32_t*)&qs[(m0 + grp    ) * ASTH + kk * 16 + 2 * tig];
        const uint32_t* r1 = (const uint32_t*)&qs[(m0 + grp + 8) * ASTH + kk * 16 + 2 * tig];
        qa[kk][0] = r0[0];
        qa[kk][1] = r1[0];
        qa[kk][2] = r0[4];
        qa[kk][3] = r1[4];
    }

    float mrow[2] = {-1e30f, -1e30f};
    float lrow[2] = {0.f, 0.f};
    float oc[8][4];
#pragma unroll
    for (int nt = 0; nt < 8; nt++)
#pragma unroll
        for (int c = 0; c < 4; c++) oc[nt][c] = 0.f;

    int ntl = L >> 6;
    for (int kt = 0; kt < ntl; kt++) {
        if (kt > 0) {
            __syncthreads();
            stage_kv(kt);
            __syncthreads();
        }

        float sacc[8][4];
#pragma unroll
        for (int nt = 0; nt < 8; nt++)
#pragma unroll
            for (int c = 0; c < 4; c++) sacc[nt][c] = 0.f;
#pragma unroll
        for (int kk = 0; kk < 4; kk++) {
#pragma unroll
            for (int nt = 0; nt < 8; nt++) {
                const uint32_t* kr = (const uint32_t*)&ks[(nt * 8 + grp) * ASTH + kk * 16 + 2 * tig];
                mma_f16(sacc[nt], qa[kk][0], qa[kk][1], qa[kk][2], qa[kk][3],
                        kr[0], kr[4]);
            }
        }

        float mx0 = -1e30f, mx1 = -1e30f;
#pragma unroll
        for (int nt = 0; nt < 8; nt++) {
            mx0 = fmaxf(mx0, fmaxf(sacc[nt][0], sacc[nt][1]));
            mx1 = fmaxf(mx1, fmaxf(sacc[nt][2], sacc[nt][3]));
        }
        mx0 = fmaxf(mx0, __shfl_xor_sync(0xffffffffu, mx0, 1));
        mx0 = fmaxf(mx0, __shfl_xor_sync(0xffffffffu, mx0, 2));
        mx1 = fmaxf(mx1, __shfl_xor_sync(0xffffffffu, mx1, 1));
        mx1 = fmaxf(mx1, __shfl_xor_sync(0xffffffffu, mx1, 2));
        float nm0 = fmaxf(mrow[0], mx0), nm1 = fmaxf(mrow[1], mx1);
        float al0 = fexp(mrow[0] - nm0),  al1 = fexp(mrow[1] - nm1);
        float s0 = 0.f, s1 = 0.f;
#pragma unroll
        for (int nt = 0; nt < 8; nt++) {
            float p0 = fexp(sacc[nt][0] - nm0);
            float p1 = fexp(sacc[nt][1] - nm0);
            float p2 = fexp(sacc[nt][2] - nm1);
            float p3 = fexp(sacc[nt][3] - nm1);
            s0 += p0 + p1;
            s1 += p2 + p3;
            *(__half2*)&ps[(m0 + grp    ) * ASTH + nt * 8 + 2 * tig] =
                __floats2half2_rn(p0, p1);
            *(__half2*)&ps[(m0 + grp + 8) * ASTH + nt * 8 + 2 * tig] =
                __floats2half2_rn(p2, p3);
        }
        s0 += __shfl_xor_sync(0xffffffffu, s0, 1);
        s0 += __shfl_xor_sync(0xffffffffu, s0, 2);
        s1 += __shfl_xor_sync(0xffffffffu, s1, 1);
        s1 += __shfl_xor_sync(0xffffffffu, s1, 2);
        lrow[0] = lrow[0] * al0 + s0;
        lrow[1] = lrow[1] * al1 + s1;
        mrow[0] = nm0; mrow[1] = nm1;
#pragma unroll
        for (int nt = 0; nt < 8; nt++) {
            oc[nt][0] *= al0; oc[nt][1] *= al0;
            oc[nt][2] *= al1; oc[nt][3] *= al1;
        }
        __syncwarp();

#pragma unroll
        for (int kk = 0; kk < 4; kk++) {
            const uint32_t* p0 = (const uint32_t*)&ps[(m0 + grp    ) * ASTH + kk * 16 + 2 * tig];
            const uint32_t* p1 = (const uint32_t*)&ps[(m0 + grp + 8) * ASTH + kk * 16 + 2 * tig];
            uint32_t pa0 = p0[0], pa1 = p1[0], pa2 = p0[4], pa3 = p1[4];
#pragma unroll
            for (int nt = 0; nt < 8; nt++) {
                const uint32_t* vr = (const uint32_t*)&vsT[(nt * 8 + grp) * ASTH + kk * 16 + 2 * tig];
                mma_f16(oc[nt], pa0, pa1, pa2, pa3, vr[0], vr[4]);
            }
        }
        __syncwarp();
    }

    float i0 = 1.0f / lrow[0], i1 = 1.0f / lrow[1];
    size_t tok0 = seq_base + qbase + m0 + grp;
#pragma unroll
    for (int nt = 0; nt < 8; nt++) {
        int col = h * DH + nt * 8 + 2 * tig;
        *(__half2*)&ctx[tok0 * INNER + col] =
            __floats2half2_rn(oc[nt][0] * i0, oc[nt][1] * i0);
        *(__half2*)&ctx[(tok0 + 8) * INNER + col] =
            __floats2half2_rn(oc[nt][2] * i1, oc[nt][3] * i1);
    }
}

// ---------------------------------------------------------------------------
// Host launch
// ---------------------------------------------------------------------------
extern "C" void kernel_launch(void* const* d_in, const int* in_sizes, int n_in,
                              void* d_out, int out_size)
{
    const float* x_in    = (const float*)d_in[0];
    const float* ln_s_g  = (const float*)d_in[1];
    const float* ln_s_b  = (const float*)d_in[2];
    const float* w_qkv_s = (const float*)d_in[3];
    const float* w_out_s = (const float*)d_in[4];
    const float* b_out_s = (const float*)d_in[5];
    const float* ln_t_g  = (const float*)d_in[6];
    const float* ln_t_b  = (const float*)d_in[7];
    const float* w_qkv_t = (const float*)d_in[8];
    const float* w_out_t = (const float*)d_in[9];
    const float* b_out_t = (const float*)d_in[10];
    const float* ln_f_g  = (const float*)d_in[11];
    const float* ln_f_b  = (const float*)d_in[12];
    float* x = (float*)d_out;

    cudaFuncSetAttribute(hgemm_kernel, cudaFuncAttributeMaxDynamicSharedMemorySize,
                         HGEMM_SMEM);

    __half *qkv_p, *ctx_p, *xs_p, *xt_p;
    uint32_t* wp_p;
    cudaGetSymbolAddress((void**)&qkv_p, g_qkv);
    cudaGetSymbolAddress((void**)&ctx_p, g_ctx);
    cudaGetSymbolAddress((void**)&xs_p,  g_xs);
    cudaGetSymbolAddress((void**)&xt_p,  g_xt);
    cudaGetSymbolAddress((void**)&wp_p,  g_wp);
    __half* ln_p = ctx_p;

    uint32_t* wp_qkv_s = wp_p;
    uint32_t* wp_out_s = wp_p + WQKV_SZ / 2;
    uint32_t* wp_qkv_t = wp_p + (WQKV_SZ + WOUT_SZ) / 2;
    uint32_t* wp_out_t = wp_p + WQKV_SZ + WOUT_SZ / 2;

    cudaMemcpyAsync(x, x_in, (size_t)NTOK * DD * sizeof(float),
                    cudaMemcpyDeviceToDevice);
    rope_table_kernel<<<(256 * 32 + 255) / 256, 256>>>();
    pack_all_kernel<<<dim3(((DD / 2) * QKV3 + 255) / 256, DEPTH, 4), 256>>>(
        w_qkv_s, w_out_s, w_qkv_t, w_out_t, wp_p);

    dim3 ln_grid(NTOK / 8);
    dim3 gemm_qkv_grid(NTOK / 128, QKV3 / 128);
    dim3 gemm_out_grid(NTOK / 128, DD / 128);
    dim3 attn_s_grid(PP / 128, HH, BB * TT);   // 128-query blocks, 256 threads
    dim3 attn_t_grid(TT / 64, HH, BB * PP);    // 64-query blocks, 128 threads

    for (int i = 0; i < DEPTH; i++) {
        const uint32_t* wq_s = wp_qkv_s + (size_t)i * (DD / 2) * QKV3;
        const uint32_t* wo_s = wp_out_s + (size_t)i * (INNER / 2) * DD;
        const uint32_t* wq_t = wp_qkv_t + (size_t)i * (DD / 2) * QKV3;
        const uint32_t* wo_t = wp_out_t + (size_t)i * (INNER / 2) * DD;

        // ---- spatial branch ----
        ln_kernel<<<ln_grid, 256>>>(x, ln_s_g + i * DD, ln_s_b + i * DD, ln_p);
        hgemm_kernel<<<gemm_qkv_grid, 256, HGEMM_SMEM>>>(ln_p, wq_s, nullptr, qkv_p,
                                                         NTOK, QKV3, DD);
        attn_tc_kernel<<<attn_s_grid, 256>>>(qkv_p, ctx_p, PP);
        hgemm_kernel<<<gemm_out_grid, 256, HGEMM_SMEM>>>(ctx_p, wo_s, b_out_s + i * DD, xs_p,
                                                         NTOK, DD, INNER);

        // ---- temporal branch ----
        ln_add_transpose_kernel<<<ln_grid, 256>>>(x, xs_p, ln_t_g + i * DD,
                                                  ln_t_b + i * DD, ln_p);
        hgemm_kernel<<<gemm_qkv_grid, 256, HGEMM_SMEM>>>(ln_p, wq_t, nullptr, qkv_p,
                                                         NTOK, QKV3, DD);
        attn_tc_kernel<<<attn_t_grid, 128>>>(qkv_p, ctx_p, TT);
        hgemm_kernel<<<gemm_out_grid, 256, HGEMM_SMEM>>>(ctx_p, wo_t, b_out_t + i * DD, xt_p,
                                                         NTOK, DD, INNER);

        // ---- finish ----
        ln_final_kernel<<<ln_grid, 256>>>(xs_p, xt_p, ln_f_g + i * DD,
                                          ln_f_b + i * DD, x);
    }
}

// round 15
// speedup vs baseline: 1.1200x; 1.1200x over previous
#include <cuda_runtime.h>
#include <cuda_bf16.h>
#include <cuda_fp16.h>
#include <math.h>
#include <stdint.h>

// ---------------------------------------------------------------------------
// Problem constants
// ---------------------------------------------------------------------------
#define BB    2
#define TT    64
#define PP    256
#define DD    512
#define HH    8
#define DH    64
#define INNER 512          // HH*DH
#define QKV3  1536         // 3*INNER
#define NTOK  32768        // BB*TT*PP
#define DEPTH 4
#define LN_EPS 1e-5f

#define WQKV_SZ (DEPTH * DD * QKV3)
#define WOUT_SZ (DEPTH * INNER * DD)

// ---------------------------------------------------------------------------
// Static device scratch (qkv/ctx/xs/xt fp16; x residual stays fp32)
// ---------------------------------------------------------------------------
__device__ __half   g_qkv[(size_t)NTOK * QKV3];
__device__ __half   g_ctx[(size_t)NTOK * INNER];
__device__ __half   g_xs [(size_t)NTOK * DD];
__device__ __half   g_xt [(size_t)NTOK * DD];
__device__ uint32_t g_wp [WQKV_SZ + WOUT_SZ];   // k-pair-packed fp16 weights
__device__ float    g_cos[256 * 32];
__device__ float    g_sin[256 * 32];

// ---------------------------------------------------------------------------
// RoPE table
// ---------------------------------------------------------------------------
__global__ void rope_table_kernel() {
    int i = blockIdx.x * blockDim.x + threadIdx.x;
    if (i >= 256 * 32) return;
    int pos = i >> 5;
    int j   = i & 31;
    float freq  = powf(10000.0f, -(float)(2 * j) / 64.0f);
    float theta = (float)pos * freq;
    float s, c;
    sincosf(theta, &s, &c);
    g_cos[i] = c;
    g_sin[i] = s;
}

// ---------------------------------------------------------------------------
// Fast exp on the FMA pipe
// ---------------------------------------------------------------------------
__device__ __forceinline__ float fexp(float x) {
    x = fmaxf(x, -80.0f);
    float y = x * 1.44269504088896340736f;
    float t = y + 12582912.0f;
    int   n = __float_as_int(t) - 0x4B400000;
    float f = y - (t - 12582912.0f);
    float p =             1.54035303933e-4f;
    p = fmaf(p, f, 1.33335581464e-3f);
    p = fmaf(p, f, 9.61812910763e-3f);
    p = fmaf(p, f, 5.55041086648e-2f);
    p = fmaf(p, f, 2.40226506959e-1f);
    p = fmaf(p, f, 6.93147180560e-1f);
    p = fmaf(p, f, 1.0f);
    return p * __int_as_float((n + 127) << 23);
}

__device__ __forceinline__ void mma_f16(float c[4],
                                        uint32_t a0, uint32_t a1, uint32_t a2, uint32_t a3,
                                        uint32_t b0, uint32_t b1)
{
    asm volatile(
        "mma.sync.aligned.m16n8k16.row.col.f32.f16.f16.f32 "
        "{%0,%1,%2,%3}, {%4,%5,%6,%7}, {%8,%9}, {%0,%1,%2,%3};"
        : "+f"(c[0]), "+f"(c[1]), "+f"(c[2]), "+f"(c[3])
        : "r"(a0), "r"(a1), "r"(a2), "r"(a3), "r"(b0), "r"(b1));
}

__device__ __forceinline__ void ldsm_x4(uint32_t r[4], uint32_t addr) {
    asm volatile("ldmatrix.sync.aligned.m8n8.x4.shared.b16 {%0,%1,%2,%3}, [%4];"
        : "=r"(r[0]), "=r"(r[1]), "=r"(r[2]), "=r"(r[3]) : "r"(addr));
}

__device__ __forceinline__ void cp_async16(uint32_t dst, const void* src) {
    asm volatile("cp.async.cg.shared.global [%0], [%1], 16;\n" :: "r"(dst), "l"(src));
}

// ---------------------------------------------------------------------------
// Fused weight prep: all 4 groups x 4 layers in one launch.
// ---------------------------------------------------------------------------
__global__ void pack_all_kernel(const float* __restrict__ wq_s,
                                const float* __restrict__ wo_s,
                                const float* __restrict__ wq_t,
                                const float* __restrict__ wo_t,
                                uint32_t* __restrict__ dst_base)
{
    int grpi = blockIdx.z;
    int z    = blockIdx.y;
    int K2 = (grpi & 1) ? (INNER / 2) : (DD / 2);
    int N  = (grpi & 1) ? DD : QKV3;
    int i = blockIdx.x * blockDim.x + threadIdx.x;
    if (i >= K2 * N) return;
    const float* src = (grpi == 0) ? wq_s : (grpi == 1) ? wo_s : (grpi == 2) ? wq_t : wo_t;
    size_t dsto = (grpi == 0) ? 0
                : (grpi == 1) ? (size_t)WQKV_SZ / 2
                : (grpi == 2) ? (size_t)(WQKV_SZ + WOUT_SZ) / 2
                :               (size_t)WQKV_SZ + WOUT_SZ / 2;
    const float* s = src + (size_t)z * 2 * K2 * N;
    int k2 = i / N, n = i - k2 * N;
    __half2 h = __floats2half2_rn(s[(size_t)(2 * k2) * N + n],
                                  s[(size_t)(2 * k2 + 1) * N + n]);
    dst_base[dsto + (size_t)z * K2 * N + i] = *(uint32_t*)&h;
}

// ---------------------------------------------------------------------------
// Warp-per-row LayerNorm over D=512
// ---------------------------------------------------------------------------
__device__ __forceinline__ void warp_ln_core(
    const float4 v[4], int lane,
    const float* __restrict__ g, const float* __restrict__ b,
    float4 o[4])
{
    float s = 0.f, s2 = 0.f;
#pragma unroll
    for (int i = 0; i < 4; i++) {
        s  += v[i].x + v[i].y + v[i].z + v[i].w;
        s2 += v[i].x * v[i].x + v[i].y * v[i].y + v[i].z * v[i].z + v[i].w * v[i].w;
    }
#pragma unroll
    for (int o_ = 16; o_ > 0; o_ >>= 1) {
        s  += __shfl_xor_sync(0xffffffffu, s,  o_);
        s2 += __shfl_xor_sync(0xffffffffu, s2, o_);
    }
    float mu   = s * (1.0f / 512.0f);
    float var  = s2 * (1.0f / 512.0f) - mu * mu;
    float rstd = rsqrtf(var + LN_EPS);
#pragma unroll
    for (int i = 0; i < 4; i++) {
        int c = (lane + 32 * i) * 4;
        float4 gg = *(const float4*)(g + c);
        float4 bb = *(const float4*)(b + c);
        o[i].x = (v[i].x - mu) * rstd * gg.x + bb.x;
        o[i].y = (v[i].y - mu) * rstd * gg.y + bb.y;
        o[i].z = (v[i].z - mu) * rstd * gg.z + bb.z;
        o[i].w = (v[i].w - mu) * rstd * gg.w + bb.w;
    }
}

__device__ __forceinline__ void store_half4(__half* p, float4 o) {
    __half2 ha = __floats2half2_rn(o.x, o.y);
    __half2 hb = __floats2half2_rn(o.z, o.w);
    uint2 pk = make_uint2(*(uint32_t*)&ha, *(uint32_t*)&hb);
    *(uint2*)p = pk;
}

__device__ __forceinline__ float4 load_half4(const __half* p) {
    uint2 pk = *(const uint2*)p;
    __half2 ha = *(__half2*)&pk.x;
    __half2 hb = *(__half2*)&pk.y;
    return make_float4(__half2float(__low2half(ha)), __half2float(__high2half(ha)),
                       __half2float(__low2half(hb)), __half2float(__high2half(hb)));
}

__global__ void ln_kernel(const float* __restrict__ x,
                          const float* __restrict__ g, const float* __restrict__ b,
                          __half* __restrict__ out)
{
    int row  = blockIdx.x * 8 + (threadIdx.x >> 5);
    int lane = threadIdx.x & 31;
    const float* xr = x + (size_t)row * DD;
    float4 v[4];
#pragma unroll
    for (int i = 0; i < 4; i++) v[i] = *(const float4*)(xr + (lane + 32 * i) * 4);
    float4 o[4];
    warp_ln_core(v, lane, g, b, o);
    __half* orow = out + (size_t)row * DD;
#pragma unroll
    for (int i = 0; i < 4; i++) store_half4(orow + (lane + 32 * i) * 4, o[i]);
}

__global__ void ln_add_transpose_kernel(const float* __restrict__ x,
                                        const __half* __restrict__ xs,
                                        const float* __restrict__ g, const float* __restrict__ b,
                                        __half* __restrict__ out)
{
    int row  = blockIdx.x * 8 + (threadIdx.x >> 5);
    int lane = threadIdx.x & 31;
    int t_ = row & 63;
    int p_ = (row >> 6) & 255;
    int b_ = row >> 14;
    int src = (b_ * TT + t_) * PP + p_;
    const float* xr   = x  + (size_t)src * DD;
    const __half* xsr = xs + (size_t)src * DD;
    float4 v[4];
#pragma unroll
    for (int i = 0; i < 4; i++) {
        float4 a = *(const float4*)(xr + (lane + 32 * i) * 4);
        float4 c = load_half4(xsr + (lane + 32 * i) * 4);
        v[i].x = a.x + c.x; v[i].y = a.y + c.y; v[i].z = a.z + c.z; v[i].w = a.w + c.w;
    }
    float4 o[4];
    warp_ln_core(v, lane, g, b, o);
    __half* orow = out + (size_t)row * DD;
#pragma unroll
    for (int i = 0; i < 4; i++) store_half4(orow + (lane + 32 * i) * 4, o[i]);
}

__global__ void ln_final_kernel(const __half* __restrict__ xs,
                                const __half* __restrict__ xt,
                                const float* __restrict__ g, const float* __restrict__ b,
                                float* __restrict__ x)
{
    int row  = blockIdx.x * 8 + (threadIdx.x >> 5);
    int lane = threadIdx.x & 31;
    int p_ = row & 255;
    int t_ = (row >> 8) & 63;
    int b_ = row >> 14;
    int xtr = (b_ * PP + p_) * TT + t_;
    const __half* xsr   = xs + (size_t)row * DD;
    const __half* xtr_p = xt + (size_t)xtr * DD;
    float* xr = x + (size_t)row * DD;
    float4 v[4], xv[4];
#pragma unroll
    for (int i = 0; i < 4; i++) {
        float4 a = load_half4(xsr   + (lane + 32 * i) * 4);
        float4 c = load_half4(xtr_p + (lane + 32 * i) * 4);
        v[i].x = a.x + c.x; v[i].y = a.y + c.y; v[i].z = a.z + c.z; v[i].w = a.w + c.w;
        xv[i] = *(const float4*)(xr + (lane + 32 * i) * 4);
    }
    float4 o[4];
    warp_ln_core(v, lane, g, b, o);
#pragma unroll
    for (int i = 0; i < 4; i++) {
        o[i].x += xv[i].x; o[i].y += xv[i].y; o[i].z += xv[i].z; o[i].w += xv[i].w;
        *(float4*)(xr + (lane + 32 * i) * 4) = o[i];
    }
}

// ---------------------------------------------------------------------------
// fp16 tensor-core GEMM, 128x128x64 tile, A-fragments via ldmatrix.x4.
// ---------------------------------------------------------------------------
#define HA_STR 72
#define HB_STR 136
#define HA_BUF (128 * HA_STR)
#define HB_BUF (32 * HB_STR)
#define HGEMM_SMEM (2 * HA_BUF * 2 + 2 * HB_BUF * 4)

__global__ void __launch_bounds__(256, 2) hgemm_kernel(
    const __half* __restrict__ A, const uint32_t* __restrict__ Bp,
    const float* __restrict__ bias, __half* __restrict__ C,
    int M, int N, int K)
{
    extern __shared__ char smem[];
    uint32_t* Bs = (uint32_t*)(smem + 2 * HA_BUF * 2);

    int tid  = threadIdx.x;
    int lane = tid & 31;
    int wid  = tid >> 5;
    int wm   = wid >> 2;
    int wn   = wid & 3;
    int grp  = lane >> 2;
    int tig  = lane & 3;
    int bm = blockIdx.x, bn = blockIdx.y;

    const __half*   Ag = A  + (size_t)bm * 128 * K;
    const uint32_t* Bg = Bp + bn * 128;

    uint32_t as_base = (uint32_t)__cvta_generic_to_shared(smem);
    uint32_t bs_base = (uint32_t)__cvta_generic_to_shared(Bs);

    // ldmatrix lane address offset within an A fragment (bytes)
    int row_l = (lane & 7) + ((lane >> 3) & 1) * 8;
    int col_l = (lane >> 4) * 8;
    uint32_t a_lane_off = (uint32_t)(row_l * HA_STR + col_l) * 2;

    float acc[4][4][4];
#pragma unroll
    for (int i = 0; i < 4; i++)
#pragma unroll
        for (int j = 0; j < 4; j++)
#pragma unroll
            for (int c = 0; c < 4; c++) acc[i][j][c] = 0.f;

    const int NK = K / 64;

    auto load_tiles = [&](int kt, int buf) {
#pragma unroll
        for (int it = 0; it < 4; it++) {
            int slot = tid + it * 256;
            int row  = slot >> 3;
            int seg  = slot & 7;
            uint32_t dst = as_base + buf * (HA_BUF * 2) + row * (HA_STR * 2) + seg * 16;
            cp_async16(dst, Ag + (size_t)row * K + kt * 64 + seg * 8);
        }
#pragma unroll
        for (int it = 0; it < 4; it++) {
            int slot = tid + it * 256;
            int row  = slot >> 5;
            int seg  = slot & 31;
            uint32_t dst = bs_base + buf * (HB_BUF * 4) + row * (HB_STR * 4) + seg * 16;
            cp_async16(dst, Bg + (size_t)(kt * 32 + row) * N + seg * 4);
        }
        asm volatile("cp.async.commit_group;\n");
    };

    load_tiles(0, 0);

    for (int kt = 0; kt < NK; kt++) {
        int buf = kt & 1;
        if (kt + 1 < NK) {
            load_tiles(kt + 1, buf ^ 1);
            asm volatile("cp.async.wait_group 1;\n");
        } else {
            asm volatile("cp.async.wait_group 0;\n");
        }
        __syncthreads();

        uint32_t a_base = as_base + buf * (HA_BUF * 2)
                        + (uint32_t)(wm * 64) * (HA_STR * 2) + a_lane_off;
        const uint32_t* bs = Bs + buf * HB_BUF;

#pragma unroll
        for (int ks = 0; ks < 4; ks++) {
            uint32_t af[4][4];
#pragma unroll
            for (int mt = 0; mt < 4; mt++)
                ldsm_x4(af[mt], a_base + (uint32_t)(mt * 16) * (HA_STR * 2) + ks * 32);
            uint32_t bf[4][2];
#pragma unroll
            for (int nt = 0; nt < 4; nt++) {
                int n = wn * 32 + nt * 8;
                bf[nt][0] = bs[(ks * 8 + tig    ) * HB_STR + n + grp];
                bf[nt][1] = bs[(ks * 8 + tig + 4) * HB_STR + n + grp];
            }
#pragma unroll
            for (int mt = 0; mt < 4; mt++)
#pragma unroll
                for (int nt = 0; nt < 4; nt++)
                    mma_f16(acc[mt][nt], af[mt][0], af[mt][1], af[mt][2], af[mt][3],
                            bf[nt][0], bf[nt][1]);
        }
        __syncthreads();
    }

#pragma unroll
    for (int nt = 0; nt < 4; nt++) {
        int colg = bn * 128 + wn * 32 + nt * 8 + 2 * tig;
        float2 bv = {0.f, 0.f};
        if (bias) bv = *(const float2*)(bias + colg);
#pragma unroll
        for (int mt = 0; mt < 4; mt++) {
            int row0 = bm * 128 + wm * 64 + mt * 16 + grp;
            *(__half2*)(C + (size_t)row0 * N + colg) =
                __floats2half2_rn(acc[mt][nt][0] + bv.x, acc[mt][nt][1] + bv.y);
            *(__half2*)(C + (size_t)(row0 + 8) * N + colg) =
                __floats2half2_rn(acc[mt][nt][2] + bv.x, acc[mt][nt][3] + bv.y);
        }
    }
}

// ---------------------------------------------------------------------------
// fp16 tensor-core flash attention, compile-time warp count NW.
// Block handles NW*16 queries; warp w owns 16 q-rows. KV tiles of 64.
// NW=8: spatial (KV staged once per 128 queries). NW=4: temporal.
// ---------------------------------------------------------------------------
#define ASTH 72                 // halves per tile row

template <int NW>
__global__ void __launch_bounds__(NW * 32, (NW == 8) ? 2 : 4) attn_tc_kernel(
    const __half* __restrict__ qkv, __half* __restrict__ ctx, int L)
{
    constexpr int NTHR = NW * 32;
    constexpr int QT   = NW * 16;
    __shared__ __half qs [QT * ASTH];    // doubles as ps
    __shared__ __half ks [64 * ASTH];
    __shared__ __half vsT[64 * ASTH];
    __half* ps = qs;

    int tid  = threadIdx.x;
    int lane = tid & 31;
    int w    = tid >> 5;
    int grp  = lane >> 2;
    int tig  = lane & 3;
    int qt = blockIdx.x, h = blockIdx.y;
    size_t seq_base = (size_t)blockIdx.z * L;
    int qbase = qt * QT;
    int m0 = w * 16;

    // ---- stage Q (rotary + scale -> fp16): QT*32 pairs, 16 iters ----
#pragma unroll
    for (int it = 0; it < 16; it++) {
        int slot = it * NTHR + tid;
        int row = slot >> 5, pr = slot & 31;
        int pos = qbase + row;
        const __half* p = qkv + (seq_base + pos) * QKV3 + h * DH + 2 * pr;
        __half2 qh = *(const __half2*)p;
        float qx = __half2float(__low2half(qh)), qy = __half2float(__high2half(qh));
        float c = g_cos[pos * 32 + pr], sn = g_sin[pos * 32 + pr];
        float e0 = (qx * c - qy * sn) * 0.125f;
        float e1 = (qy * c + qx * sn) * 0.125f;
        *(__half2*)&qs[row * ASTH + 2 * pr] = __floats2half2_rn(e0, e1);
    }

    auto stage_kv = [&](int kt) {
#pragma unroll
        for (int it = 0; it < 2048 / NTHR; it++) {
            int slot = it * NTHR + tid;
            int row = slot >> 5, pr = slot & 31;
            int pos = kt * 64 + row;
            const __half* p = qkv + (seq_base + pos) * QKV3 + INNER + h * DH + 2 * pr;
            __half2 kh = *(const __half2*)p;
            float kx = __half2float(__low2half(kh)), ky = __half2float(__high2half(kh));
            float c = g_cos[pos * 32 + pr], sn = g_sin[pos * 32 + pr];
            float e0 = kx * c - ky * sn;
            float e1 = ky * c + kx * sn;
            *(__half2*)&ks[row * ASTH + 2 * pr] = __floats2half2_rn(e0, e1);
        }
#pragma unroll
        for (int it = 0; it < 2048 / NTHR; it++) {
            int slot = it * NTHR + tid;
            int d  = slot & 63;
            int pp = slot >> 6;
            const __half* p = qkv + (seq_base + kt * 64 + 2 * pp) * QKV3
                            + 2 * INNER + h * DH + d;
            __half v0 = p[0];
            __half v1 = p[QKV3];
            *(__half2*)&vsT[d * ASTH + 2 * pp] = __halves2half2(v0, v1);
        }
    };

    stage_kv(0);
    __syncthreads();

    uint32_t qa[4][4];
#pragma unroll
    for (int kk = 0; kk < 4; kk++) {
        const uint32_t* r0 = (const uint32_t*)&qs[(m0 + grp    ) * ASTH + kk * 16 + 2 * tig];
        const uint32_t* r1 = (const uint32_t*)&qs[(m0 + grp + 8) * ASTH + kk * 16 + 2 * tig];
        qa[kk][0] = r0[0];
        qa[kk][1] = r1[0];
        qa[kk][2] = r0[4];
        qa[kk][3] = r1[4];
    }

    float mrow[2] = {-1e30f, -1e30f};
    float lrow[2] = {0.f, 0.f};
    float oc[8][4];
#pragma unroll
    for (int nt = 0; nt < 8; nt++)
#pragma unroll
        for (int c = 0; c < 4; c++) oc[nt][c] = 0.f;

    int ntl = L >> 6;
    for (int kt = 0; kt < ntl; kt++) {
        if (kt > 0) {
            __syncthreads();
            stage_kv(kt);
            __syncthreads();
        }

        float sacc[8][4];
#pragma unroll
        for (int nt = 0; nt < 8; nt++)
#pragma unroll
            for (int c = 0; c < 4; c++) sacc[nt][c] = 0.f;
#pragma unroll
        for (int kk = 0; kk < 4; kk++) {
#pragma unroll
            for (int nt = 0; nt < 8; nt++) {
                const uint32_t* kr = (const uint32_t*)&ks[(nt * 8 + grp) * ASTH + kk * 16 + 2 * tig];
                mma_f16(sacc[nt], qa[kk][0], qa[kk][1], qa[kk][2], qa[kk][3],
                        kr[0], kr[4]);
            }
        }

        float mx0 = -1e30f, mx1 = -1e30f;
#pragma unroll
        for (int nt = 0; nt < 8; nt++) {
            mx0 = fmaxf(mx0, fmaxf(sacc[nt][0], sacc[nt][1]));
            mx1 = fmaxf(mx1, fmaxf(sacc[nt][2], sacc[nt][3]));
        }
        mx0 = fmaxf(mx0, __shfl_xor_sync(0xffffffffu, mx0, 1));
        mx0 = fmaxf(mx0, __shfl_xor_sync(0xffffffffu, mx0, 2));
        mx1 = fmaxf(mx1, __shfl_xor_sync(0xffffffffu, mx1, 1));
        mx1 = fmaxf(mx1, __shfl_xor_sync(0xffffffffu, mx1, 2));
        float nm0 = fmaxf(mrow[0], mx0), nm1 = fmaxf(mrow[1], mx1);
        float al0 = fexp(mrow[0] - nm0),  al1 = fexp(mrow[1] - nm1);
        float s0 = 0.f, s1 = 0.f;
#pragma unroll
        for (int nt = 0; nt < 8; nt++) {
            float p0 = fexp(sacc[nt][0] - nm0);
            float p1 = fexp(sacc[nt][1] - nm0);
            float p2 = fexp(sacc[nt][2] - nm1);
            float p3 = fexp(sacc[nt][3] - nm1);
            s0 += p0 + p1;
            s1 += p2 + p3;
            *(__half2*)&ps[(m0 + grp    ) * ASTH + nt * 8 + 2 * tig] =
                __floats2half2_rn(p0, p1);
            *(__half2*)&ps[(m0 + grp + 8) * ASTH + nt * 8 + 2 * tig] =
                __floats2half2_rn(p2, p3);
        }
        s0 += __shfl_xor_sync(0xffffffffu, s0, 1);
        s0 += __shfl_xor_sync(0xffffffffu, s0, 2);
        s1 += __shfl_xor_sync(0xffffffffu, s1, 1);
        s1 += __shfl_xor_sync(0xffffffffu, s1, 2);
        lrow[0] = lrow[0] * al0 + s0;
        lrow[1] = lrow[1] * al1 + s1;
        mrow[0] = nm0; mrow[1] = nm1;
#pragma unroll
        for (int nt = 0; nt < 8; nt++) {
            oc[nt][0] *= al0; oc[nt][1] *= al0;
            oc[nt][2] *= al1; oc[nt][3] *= al1;
        }
        __syncwarp();

#pragma unroll
        for (int kk = 0; kk < 4; kk++) {
            const uint32_t* p0 = (const uint32_t*)&ps[(m0 + grp    ) * ASTH + kk * 16 + 2 * tig];
            const uint32_t* p1 = (const uint32_t*)&ps[(m0 + grp + 8) * ASTH + kk * 16 + 2 * tig];
            uint32_t pa0 = p0[0], pa1 = p1[0], pa2 = p0[4], pa3 = p1[4];
#pragma unroll
            for (int nt = 0; nt < 8; nt++) {
                const uint32_t* vr = (const uint32_t*)&vsT[(nt * 8 + grp) * ASTH + kk * 16 + 2 * tig];
                mma_f16(oc[nt], pa0, pa1, pa2, pa3, vr[0], vr[4]);
            }
        }
        __syncwarp();
    }

    float i0 = 1.0f / lrow[0], i1 = 1.0f / lrow[1];
    size_t tok0 = seq_base + qbase + m0 + grp;
#pragma unroll
    for (int nt = 0; nt < 8; nt++) {
        int col = h * DH + nt * 8 + 2 * tig;
        *(__half2*)&ctx[tok0 * INNER + col] =
            __floats2half2_rn(oc[nt][0] * i0, oc[nt][1] * i0);
        *(__half2*)&ctx[(tok0 + 8) * INNER + col] =
            __floats2half2_rn(oc[nt][2] * i1, oc[nt][3] * i1);
    }
}

// ---------------------------------------------------------------------------
// Host launch
// ---------------------------------------------------------------------------
extern "C" void kernel_launch(void* const* d_in, const int* in_sizes, int n_in,
                              void* d_out, int out_size)
{
    const float* x_in    = (const float*)d_in[0];
    const float* ln_s_g  = (const float*)d_in[1];
    const float* ln_s_b  = (const float*)d_in[2];
    const float* w_qkv_s = (const float*)d_in[3];
    const float* w_out_s = (const float*)d_in[4];
    const float* b_out_s = (const float*)d_in[5];
    const float* ln_t_g  = (const float*)d_in[6];
    const float* ln_t_b  = (const float*)d_in[7];
    const float* w_qkv_t = (const float*)d_in[8];
    const float* w_out_t = (const float*)d_in[9];
    const float* b_out_t = (const float*)d_in[10];
    const float* ln_f_g  = (const float*)d_in[11];
    const float* ln_f_b  = (const float*)d_in[12];
    float* x = (float*)d_out;

    cudaFuncSetAttribute(hgemm_kernel, cudaFuncAttributeMaxDynamicSharedMemorySize,
                         HGEMM_SMEM);

    __half *qkv_p, *ctx_p, *xs_p, *xt_p;
    uint32_t* wp_p;
    cudaGetSymbolAddress((void**)&qkv_p, g_qkv);
    cudaGetSymbolAddress((void**)&ctx_p, g_ctx);
    cudaGetSymbolAddress((void**)&xs_p,  g_xs);
    cudaGetSymbolAddress((void**)&xt_p,  g_xt);
    cudaGetSymbolAddress((void**)&wp_p,  g_wp);
    __half* ln_p = ctx_p;

    uint32_t* wp_qkv_s = wp_p;
    uint32_t* wp_out_s = wp_p + WQKV_SZ / 2;
    uint32_t* wp_qkv_t = wp_p + (WQKV_SZ + WOUT_SZ) / 2;
    uint32_t* wp_out_t = wp_p + WQKV_SZ + WOUT_SZ / 2;

    cudaMemcpyAsync(x, x_in, (size_t)NTOK * DD * sizeof(float),
                    cudaMemcpyDeviceToDevice);
    rope_table_kernel<<<(256 * 32 + 255) / 256, 256>>>();
    pack_all_kernel<<<dim3(((DD / 2) * QKV3 + 255) / 256, DEPTH, 4), 256>>>(
        w_qkv_s, w_out_s, w_qkv_t, w_out_t, wp_p);

    dim3 ln_grid(NTOK / 8);
    dim3 gemm_qkv_grid(NTOK / 128, QKV3 / 128);
    dim3 gemm_out_grid(NTOK / 128, DD / 128);
    dim3 attn_s_grid(PP / 128, HH, BB * TT);   // 128-query blocks, 256 threads
    dim3 attn_t_grid(TT / 64, HH, BB * PP);    // 64-query blocks, 128 threads

    for (int i = 0; i < DEPTH; i++) {
        const uint32_t* wq_s = wp_qkv_s + (size_t)i * (DD / 2) * QKV3;
        const uint32_t* wo_s = wp_out_s + (size_t)i * (INNER / 2) * DD;
        const uint32_t* wq_t = wp_qkv_t + (size_t)i * (DD / 2) * QKV3;
        const uint32_t* wo_t = wp_out_t + (size_t)i * (INNER / 2) * DD;

        // ---- spatial branch ----
        ln_kernel<<<ln_grid, 256>>>(x, ln_s_g + i * DD, ln_s_b + i * DD, ln_p);
        hgemm_kernel<<<gemm_qkv_grid, 256, HGEMM_SMEM>>>(ln_p, wq_s, nullptr, qkv_p,
                                                         NTOK, QKV3, DD);
        attn_tc_kernel<8><<<attn_s_grid, 256>>>(qkv_p, ctx_p, PP);
        hgemm_kernel<<<gemm_out_grid, 256, HGEMM_SMEM>>>(ctx_p, wo_s, b_out_s + i * DD, xs_p,
                                                         NTOK, DD, INNER);

        // ---- temporal branch ----
        ln_add_transpose_kernel<<<ln_grid, 256>>>(x, xs_p, ln_t_g + i * DD,
                                                  ln_t_b + i * DD, ln_p);
        hgemm_kernel<<<gemm_qkv_grid, 256, HGEMM_SMEM>>>(ln_p, wq_t, nullptr, qkv_p,
                                                         NTOK, QKV3, DD);
        attn_tc_kernel<4><<<attn_t_grid, 128>>>(qkv_p, ctx_p, TT);
        hgemm_kernel<<<gemm_out_grid, 256, HGEMM_SMEM>>>(ctx_p, wo_t, b_out_t + i * DD, xt_p,
                                                         NTOK, DD, INNER);

        // ---- finish ----
        ln_final_kernel<<<ln_grid, 256>>>(xs_p, xt_p, ln_f_g + i * DD,
                                          ln_f_b + i * DD, x);
    }
}

// round 16
// speedup vs baseline: 1.1466x; 1.0237x over previous
#include <cuda_runtime.h>
#include <cuda_bf16.h>
#include <cuda_fp16.h>
#include <math.h>
#include <stdint.h>

// ---------------------------------------------------------------------------
// Problem constants
// ---------------------------------------------------------------------------
#define BB    2
#define TT    64
#define PP    256
#define DD    512
#define HH    8
#define DH    64
#define INNER 512          // HH*DH
#define QKV3  1536         // 3*INNER
#define NTOK  32768        // BB*TT*PP
#define DEPTH 4
#define LN_EPS 1e-5f

#define WQKV_SZ (DEPTH * DD * QKV3)
#define WOUT_SZ (DEPTH * INNER * DD)

// ---------------------------------------------------------------------------
// Static device scratch (qkv/ctx/xs/xt fp16; x residual stays fp32)
// ---------------------------------------------------------------------------
__device__ __half   g_qkv[(size_t)NTOK * QKV3];
__device__ __half   g_ctx[(size_t)NTOK * INNER];
__device__ __half   g_xs [(size_t)NTOK * DD];
__device__ __half   g_xt [(size_t)NTOK * DD];
__device__ uint32_t g_wp [WQKV_SZ + WOUT_SZ];   // k-pair-packed fp16 weights
__device__ float    g_cos[256 * 32];
__device__ float    g_sin[256 * 32];

// ---------------------------------------------------------------------------
// RoPE table
// ---------------------------------------------------------------------------
__global__ void rope_table_kernel() {
    int i = blockIdx.x * blockDim.x + threadIdx.x;
    if (i >= 256 * 32) return;
    int pos = i >> 5;
    int j   = i & 31;
    float freq  = powf(10000.0f, -(float)(2 * j) / 64.0f);
    float theta = (float)pos * freq;
    float s, c;
    sincosf(theta, &s, &c);
    g_cos[i] = c;
    g_sin[i] = s;
}

// ---------------------------------------------------------------------------
// Fast exp on the FMA pipe
// ---------------------------------------------------------------------------
__device__ __forceinline__ float fexp(float x) {
    x = fmaxf(x, -80.0f);
    float y = x * 1.44269504088896340736f;
    float t = y + 12582912.0f;
    int   n = __float_as_int(t) - 0x4B400000;
    float f = y - (t - 12582912.0f);
    float p =             1.54035303933e-4f;
    p = fmaf(p, f, 1.33335581464e-3f);
    p = fmaf(p, f, 9.61812910763e-3f);
    p = fmaf(p, f, 5.55041086648e-2f);
    p = fmaf(p, f, 2.40226506959e-1f);
    p = fmaf(p, f, 6.93147180560e-1f);
    p = fmaf(p, f, 1.0f);
    return p * __int_as_float((n + 127) << 23);
}

__device__ __forceinline__ void mma_f16(float c[4],
                                        uint32_t a0, uint32_t a1, uint32_t a2, uint32_t a3,
                                        uint32_t b0, uint32_t b1)
{
    asm volatile(
        "mma.sync.aligned.m16n8k16.row.col.f32.f16.f16.f32 "
        "{%0,%1,%2,%3}, {%4,%5,%6,%7}, {%8,%9}, {%0,%1,%2,%3};"
        : "+f"(c[0]), "+f"(c[1]), "+f"(c[2]), "+f"(c[3])
        : "r"(a0), "r"(a1), "r"(a2), "r"(a3), "r"(b0), "r"(b1));
}

__device__ __forceinline__ void ldsm_x4(uint32_t r[4], uint32_t addr) {
    asm volatile("ldmatrix.sync.aligned.m8n8.x4.shared.b16 {%0,%1,%2,%3}, [%4];"
        : "=r"(r[0]), "=r"(r[1]), "=r"(r[2]), "=r"(r[3]) : "r"(addr));
}

__device__ __forceinline__ void cp_async16(uint32_t dst, const void* src) {
    asm volatile("cp.async.cg.shared.global [%0], [%1], 16;\n" :: "r"(dst), "l"(src));
}

// ---------------------------------------------------------------------------
// Fused weight prep: all 4 groups x 4 layers in one launch.
// ---------------------------------------------------------------------------
__global__ void pack_all_kernel(const float* __restrict__ wq_s,
                                const float* __restrict__ wo_s,
                                const float* __restrict__ wq_t,
                                const float* __restrict__ wo_t,
                                uint32_t* __restrict__ dst_base)
{
    int grpi = blockIdx.z;
    int z    = blockIdx.y;
    int K2 = (grpi & 1) ? (INNER / 2) : (DD / 2);
    int N  = (grpi & 1) ? DD : QKV3;
    int i = blockIdx.x * blockDim.x + threadIdx.x;
    if (i >= K2 * N) return;
    const float* src = (grpi == 0) ? wq_s : (grpi == 1) ? wo_s : (grpi == 2) ? wq_t : wo_t;
    size_t dsto = (grpi == 0) ? 0
                : (grpi == 1) ? (size_t)WQKV_SZ / 2
                : (grpi == 2) ? (size_t)(WQKV_SZ + WOUT_SZ) / 2
                :               (size_t)WQKV_SZ + WOUT_SZ / 2;
    const float* s = src + (size_t)z * 2 * K2 * N;
    int k2 = i / N, n = i - k2 * N;
    __half2 h = __floats2half2_rn(s[(size_t)(2 * k2) * N + n],
                                  s[(size_t)(2 * k2 + 1) * N + n]);
    dst_base[dsto + (size_t)z * K2 * N + i] = *(uint32_t*)&h;
}

// ---------------------------------------------------------------------------
// Warp-per-row LayerNorm over D=512
// ---------------------------------------------------------------------------
__device__ __forceinline__ void warp_ln_core(
    const float4 v[4], int lane,
    const float* __restrict__ g, const float* __restrict__ b,
    float4 o[4])
{
    float s = 0.f, s2 = 0.f;
#pragma unroll
    for (int i = 0; i < 4; i++) {
        s  += v[i].x + v[i].y + v[i].z + v[i].w;
        s2 += v[i].x * v[i].x + v[i].y * v[i].y + v[i].z * v[i].z + v[i].w * v[i].w;
    }
#pragma unroll
    for (int o_ = 16; o_ > 0; o_ >>= 1) {
        s  += __shfl_xor_sync(0xffffffffu, s,  o_);
        s2 += __shfl_xor_sync(0xffffffffu, s2, o_);
    }
    float mu   = s * (1.0f / 512.0f);
    float var  = s2 * (1.0f / 512.0f) - mu * mu;
    float rstd = rsqrtf(var + LN_EPS);
#pragma unroll
    for (int i = 0; i < 4; i++) {
        int c = (lane + 32 * i) * 4;
        float4 gg = *(const float4*)(g + c);
        float4 bb = *(const float4*)(b + c);
        o[i].x = (v[i].x - mu) * rstd * gg.x + bb.x;
        o[i].y = (v[i].y - mu) * rstd * gg.y + bb.y;
        o[i].z = (v[i].z - mu) * rstd * gg.z + bb.z;
        o[i].w = (v[i].w - mu) * rstd * gg.w + bb.w;
    }
}

__device__ __forceinline__ void store_half4(__half* p, float4 o) {
    __half2 ha = __floats2half2_rn(o.x, o.y);
    __half2 hb = __floats2half2_rn(o.z, o.w);
    uint2 pk = make_uint2(*(uint32_t*)&ha, *(uint32_t*)&hb);
    *(uint2*)p = pk;
}

__device__ __forceinline__ float4 load_half4(const __half* p) {
    uint2 pk = *(const uint2*)p;
    __half2 ha = *(__half2*)&pk.x;
    __half2 hb = *(__half2*)&pk.y;
    return make_float4(__half2float(__low2half(ha)), __half2float(__high2half(ha)),
                       __half2float(__low2half(hb)), __half2float(__high2half(hb)));
}

// x = x_in (copy) ; out = fp16(LN_s(x_in))   — replaces memcpy + first ln
__global__ void copy_ln_kernel(const float* __restrict__ x_in,
                               const float* __restrict__ g, const float* __restrict__ b,
                               float* __restrict__ x, __half* __restrict__ out)
{
    int row  = blockIdx.x * 8 + (threadIdx.x >> 5);
    int lane = threadIdx.x & 31;
    const float* xr = x_in + (size_t)row * DD;
    float* xw = x + (size_t)row * DD;
    float4 v[4];
#pragma unroll
    for (int i = 0; i < 4; i++) {
        v[i] = *(const float4*)(xr + (lane + 32 * i) * 4);
        *(float4*)(xw + (lane + 32 * i) * 4) = v[i];
    }
    float4 o[4];
    warp_ln_core(v, lane, g, b, o);
    __half* orow = out + (size_t)row * DD;
#pragma unroll
    for (int i = 0; i < 4; i++) store_half4(orow + (lane + 32 * i) * 4, o[i]);
}

// out = fp16(LN(x[src] + xs[src])) in (b,p,t) order
__global__ void ln_add_transpose_kernel(const float* __restrict__ x,
                                        const __half* __restrict__ xs,
                                        const float* __restrict__ g, const float* __restrict__ b,
                                        __half* __restrict__ out)
{
    int row  = blockIdx.x * 8 + (threadIdx.x >> 5);
    int lane = threadIdx.x & 31;
    int t_ = row & 63;
    int p_ = (row >> 6) & 255;
    int b_ = row >> 14;
    int src = (b_ * TT + t_) * PP + p_;
    const float* xr   = x  + (size_t)src * DD;
    const __half* xsr = xs + (size_t)src * DD;
    float4 v[4];
#pragma unroll
    for (int i = 0; i < 4; i++) {
        float4 a = *(const float4*)(xr + (lane + 32 * i) * 4);
        float4 c = load_half4(xsr + (lane + 32 * i) * 4);
        v[i].x = a.x + c.x; v[i].y = a.y + c.y; v[i].z = a.z + c.z; v[i].w = a.w + c.w;
    }
    float4 o[4];
    warp_ln_core(v, lane, g, b, o);
    __half* orow = out + (size_t)row * DD;
#pragma unroll
    for (int i = 0; i < 4; i++) store_half4(orow + (lane + 32 * i) * 4, o[i]);
}

// x = LN_f(xs + xt[perm]) + x ; optionally out = fp16(LN_s_next(x_new))
__global__ void ln_final_kernel(const __half* __restrict__ xs,
                                const __half* __restrict__ xt,
                                const float* __restrict__ g, const float* __restrict__ b,
                                float* __restrict__ x)
{
    int row  = blockIdx.x * 8 + (threadIdx.x >> 5);
    int lane = threadIdx.x & 31;
    int p_ = row & 255;
    int t_ = (row >> 8) & 63;
    int b_ = row >> 14;
    int xtr = (b_ * PP + p_) * TT + t_;
    const __half* xsr   = xs + (size_t)row * DD;
    const __half* xtr_p = xt + (size_t)xtr * DD;
    float* xr = x + (size_t)row * DD;
    float4 v[4], xv[4];
#pragma unroll
    for (int i = 0; i < 4; i++) {
        float4 a = load_half4(xsr   + (lane + 32 * i) * 4);
        float4 c = load_half4(xtr_p + (lane + 32 * i) * 4);
        v[i].x = a.x + c.x; v[i].y = a.y + c.y; v[i].z = a.z + c.z; v[i].w = a.w + c.w;
        xv[i] = *(const float4*)(xr + (lane + 32 * i) * 4);
    }
    float4 o[4];
    warp_ln_core(v, lane, g, b, o);
#pragma unroll
    for (int i = 0; i < 4; i++) {
        o[i].x += xv[i].x; o[i].y += xv[i].y; o[i].z += xv[i].z; o[i].w += xv[i].w;
        *(float4*)(xr + (lane + 32 * i) * 4) = o[i];
    }
}

// x = LN_f(xs + xt[perm]) + x ; out = fp16(LN_s_next(x_new))  (layer boundary)
__global__ void ln_final_fused_kernel(const __half* __restrict__ xs,
                                      const __half* __restrict__ xt,
                                      const float* __restrict__ gf, const float* __restrict__ bf,
                                      const float* __restrict__ gs, const float* __restrict__ bs,
                                      float* __restrict__ x, __half* __restrict__ out)
{
    int row  = blockIdx.x * 8 + (threadIdx.x >> 5);
    int lane = threadIdx.x & 31;
    int p_ = row & 255;
    int t_ = (row >> 8) & 63;
    int b_ = row >> 14;
    int xtr = (b_ * PP + p_) * TT + t_;
    const __half* xsr   = xs + (size_t)row * DD;
    const __half* xtr_p = xt + (size_t)xtr * DD;
    float* xr = x + (size_t)row * DD;
    float4 v[4], xv[4];
#pragma unroll
    for (int i = 0; i < 4; i++) {
        float4 a = load_half4(xsr   + (lane + 32 * i) * 4);
        float4 c = load_half4(xtr_p + (lane + 32 * i) * 4);
        v[i].x = a.x + c.x; v[i].y = a.y + c.y; v[i].z = a.z + c.z; v[i].w = a.w + c.w;
        xv[i] = *(const float4*)(xr + (lane + 32 * i) * 4);
    }
    float4 o[4];
    warp_ln_core(v, lane, gf, bf, o);
#pragma unroll
    for (int i = 0; i < 4; i++) {
        o[i].x += xv[i].x; o[i].y += xv[i].y; o[i].z += xv[i].z; o[i].w += xv[i].w;
        *(float4*)(xr + (lane + 32 * i) * 4) = o[i];
    }
    // second LN (next layer's spatial pre-LN) entirely in registers
    float4 o2[4];
    warp_ln_core(o, lane, gs, bs, o2);
    __half* orow = out + (size_t)row * DD;
#pragma unroll
    for (int i = 0; i < 4; i++) store_half4(orow + (lane + 32 * i) * 4, o2[i]);
}

// ---------------------------------------------------------------------------
// fp16 tensor-core GEMM, 128x128x64 tile, ldmatrix A-frags,
// 3-stage cp.async pipeline with ONE barrier per K-chunk.
// ---------------------------------------------------------------------------
#define HA_STR 72
#define HB_STR 136
#define HA_BUF (128 * HA_STR)
#define HB_BUF (32 * HB_STR)
#define STG_B  (HA_BUF * 2 + HB_BUF * 4)          // 35840 B per stage
#define HGEMM_SMEM (3 * STG_B)                     // 107520 B

__global__ void __launch_bounds__(256, 2) hgemm_kernel(
    const __half* __restrict__ A, const uint32_t* __restrict__ Bp,
    const float* __restrict__ bias, __half* __restrict__ C,
    int M, int N, int K)
{
    extern __shared__ char smem[];

    int tid  = threadIdx.x;
    int lane = tid & 31;
    int wid  = tid >> 5;
    int wm   = wid >> 2;
    int wn   = wid & 3;
    int grp  = lane >> 2;
    int tig  = lane & 3;
    int bm = blockIdx.x, bn = blockIdx.y;

    const __half*   Ag = A  + (size_t)bm * 128 * K;
    const uint32_t* Bg = Bp + bn * 128;

    uint32_t sm_base = (uint32_t)__cvta_generic_to_shared(smem);

    int row_l = (lane & 7) + ((lane >> 3) & 1) * 8;
    int col_l = (lane >> 4) * 8;
    uint32_t a_lane_off = (uint32_t)(row_l * HA_STR + col_l) * 2;

    float acc[4][4][4];
#pragma unroll
    for (int i = 0; i < 4; i++)
#pragma unroll
        for (int j = 0; j < 4; j++)
#pragma unroll
            for (int c = 0; c < 4; c++) acc[i][j][c] = 0.f;

    const int NK = K / 64;

    auto load_tiles = [&](int kt, int s) {
        uint32_t ab = sm_base + s * STG_B;
        uint32_t bb = ab + HA_BUF * 2;
#pragma unroll
        for (int it = 0; it < 4; it++) {
            int slot = tid + it * 256;
            int row  = slot >> 3;
            int seg  = slot & 7;
            cp_async16(ab + row * (HA_STR * 2) + seg * 16,
                       Ag + (size_t)row * K + kt * 64 + seg * 8);
        }
#pragma unroll
        for (int it = 0; it < 4; it++) {
            int slot = tid + it * 256;
            int row  = slot >> 5;
            int seg  = slot & 31;
            cp_async16(bb + row * (HB_STR * 4) + seg * 16,
                       Bg + (size_t)(kt * 32 + row) * N + seg * 4);
        }
        asm volatile("cp.async.commit_group;\n");
    };

    load_tiles(0, 0);
    load_tiles(1, 1);

    for (int kt = 0; kt < NK; kt++) {
        asm volatile("cp.async.wait_group 1;\n");
        __syncthreads();                 // chunk kt ready; all warps past mma kt-1

        int lc = kt + 2;
        if (lc < NK) load_tiles(lc, lc % 3);
        else asm volatile("cp.async.commit_group;\n");

        int s = kt % 3;
        uint32_t a_base = sm_base + s * STG_B
                        + (uint32_t)(wm * 64) * (HA_STR * 2) + a_lane_off;
        const uint32_t* bs = (const uint32_t*)(smem + s * STG_B + HA_BUF * 2);

#pragma unroll
        for (int ks = 0; ks < 4; ks++) {
            uint32_t af[4][4];
#pragma unroll
            for (int mt = 0; mt < 4; mt++)
                ldsm_x4(af[mt], a_base + (uint32_t)(mt * 16) * (HA_STR * 2) + ks * 32);
            uint32_t bf[4][2];
#pragma unroll
            for (int nt = 0; nt < 4; nt++) {
                int n = wn * 32 + nt * 8;
                bf[nt][0] = bs[(ks * 8 + tig    ) * HB_STR + n + grp];
                bf[nt][1] = bs[(ks * 8 + tig + 4) * HB_STR + n + grp];
            }
#pragma unroll
            for (int mt = 0; mt < 4; mt++)
#pragma unroll
                for (int nt = 0; nt < 4; nt++)
                    mma_f16(acc[mt][nt], af[mt][0], af[mt][1], af[mt][2], af[mt][3],
                            bf[nt][0], bf[nt][1]);
        }
    }

#pragma unroll
    for (int nt = 0; nt < 4; nt++) {
        int colg = bn * 128 + wn * 32 + nt * 8 + 2 * tig;
        float2 bv = {0.f, 0.f};
        if (bias) bv = *(const float2*)(bias + colg);
#pragma unroll
        for (int mt = 0; mt < 4; mt++) {
            int row0 = bm * 128 + wm * 64 + mt * 16 + grp;
            *(__half2*)(C + (size_t)row0 * N + colg) =
                __floats2half2_rn(acc[mt][nt][0] + bv.x, acc[mt][nt][1] + bv.y);
            *(__half2*)(C + (size_t)(row0 + 8) * N + colg) =
                __floats2half2_rn(acc[mt][nt][2] + bv.x, acc[mt][nt][3] + bv.y);
        }
    }
}

// ---------------------------------------------------------------------------
// fp16 tensor-core flash attention, compile-time warp count NW.
// ---------------------------------------------------------------------------
#define ASTH 72                 // halves per tile row

template <int NW>
__global__ void __launch_bounds__(NW * 32, (NW == 8) ? 2 : 4) attn_tc_kernel(
    const __half* __restrict__ qkv, __half* __restrict__ ctx, int L)
{
    constexpr int NTHR = NW * 32;
    constexpr int QT   = NW * 16;
    __shared__ __half qs [QT * ASTH];    // doubles as ps
    __shared__ __half ks [64 * ASTH];
    __shared__ __half vsT[64 * ASTH];
    __half* ps = qs;

    int tid  = threadIdx.x;
    int lane = tid & 31;
    int w    = tid >> 5;
    int grp  = lane >> 2;
    int tig  = lane & 3;
    int qt = blockIdx.x, h = blockIdx.y;
    size_t seq_base = (size_t)blockIdx.z * L;
    int qbase = qt * QT;
    int m0 = w * 16;

#pragma unroll
    for (int it = 0; it < 16; it++) {
        int slot = it * NTHR + tid;
        int row = slot >> 5, pr = slot & 31;
        int pos = qbase + row;
        const __half* p = qkv + (seq_base + pos) * QKV3 + h * DH + 2 * pr;
        __half2 qh = *(const __half2*)p;
        float qx = __half2float(__low2half(qh)), qy = __half2float(__high2half(qh));
        float c = g_cos[pos * 32 + pr], sn = g_sin[pos * 32 + pr];
        float e0 = (qx * c - qy * sn) * 0.125f;
        float e1 = (qy * c + qx * sn) * 0.125f;
        *(__half2*)&qs[row * ASTH + 2 * pr] = __floats2half2_rn(e0, e1);
    }

    auto stage_kv = [&](int kt) {
#pragma unroll
        for (int it = 0; it < 2048 / NTHR; it++) {
            int slot = it * NTHR + tid;
            int row = slot >> 5, pr = slot & 31;
            int pos = kt * 64 + row;
            const __half* p = qkv + (seq_base + pos) * QKV3 + INNER + h * DH + 2 * pr;
            __half2 kh = *(const __half2*)p;
            float kx = __half2float(__low2half(kh)), ky = __half2float(__high2half(kh));
            float c = g_cos[pos * 32 + pr], sn = g_sin[pos * 32 + pr];
            float e0 = kx * c - ky * sn;
            float e1 = ky * c + kx * sn;
            *(__half2*)&ks[row * ASTH + 2 * pr] = __floats2half2_rn(e0, e1);
        }
#pragma unroll
        for (int it = 0; it < 2048 / NTHR; it++) {
            int slot = it * NTHR + tid;
            int d  = slot & 63;
            int pp = slot >> 6;
            const __half* p = qkv + (seq_base + kt * 64 + 2 * pp) * QKV3
                            + 2 * INNER + h * DH + d;
            __half v0 = p[0];
            __half v1 = p[QKV3];
            *(__half2*)&vsT[d * ASTH + 2 * pp] = __halves2half2(v0, v1);
        }
    };

    stage_kv(0);
    __syncthreads();

    uint32_t qa[4][4];
#pragma unroll
    for (int kk = 0; kk < 4; kk++) {
        const uint32_t* r0 = (const uint32_t*)&qs[(m0 + grp    ) * ASTH + kk * 16 + 2 * tig];
        const uint32_t* r1 = (const uint32_t*)&qs[(m0 + grp + 8) * ASTH + kk * 16 + 2 * tig];
        qa[kk][0] = r0[0];
        qa[kk][1] = r1[0];
        qa[kk][2] = r0[4];
        qa[kk][3] = r1[4];
    }

    float mrow[2] = {-1e30f, -1e30f};
    float lrow[2] = {0.f, 0.f};
    float oc[8][4];
#pragma unroll
    for (int nt = 0; nt < 8; nt++)
#pragma unroll
        for (int c = 0; c < 4; c++) oc[nt][c] = 0.f;

    int ntl = L >> 6;
    for (int kt = 0; kt < ntl; kt++) {
        if (kt > 0) {
            __syncthreads();
            stage_kv(kt);
            __syncthreads();
        }

        float sacc[8][4];
#pragma unroll
        for (int nt = 0; nt < 8; nt++)
#pragma unroll
            for (int c = 0; c < 4; c++) sacc[nt][c] = 0.f;
#pragma unroll
        for (int kk = 0; kk < 4; kk++) {
#pragma unroll
            for (int nt = 0; nt < 8; nt++) {
                const uint32_t* kr = (const uint32_t*)&ks[(nt * 8 + grp) * ASTH + kk * 16 + 2 * tig];
                mma_f16(sacc[nt], qa[kk][0], qa[kk][1], qa[kk][2], qa[kk][3],
                        kr[0], kr[4]);
            }
        }

        float mx0 = -1e30f, mx1 = -1e30f;
#pragma unroll
        for (int nt = 0; nt < 8; nt++) {
            mx0 = fmaxf(mx0, fmaxf(sacc[nt][0], sacc[nt][1]));
            mx1 = fmaxf(mx1, fmaxf(sacc[nt][2], sacc[nt][3]));
        }
        mx0 = fmaxf(mx0, __shfl_xor_sync(0xffffffffu, mx0, 1));
        mx0 = fmaxf(mx0, __shfl_xor_sync(0xffffffffu, mx0, 2));
        mx1 = fmaxf(mx1, __shfl_xor_sync(0xffffffffu, mx1, 1));
        mx1 = fmaxf(mx1, __shfl_xor_sync(0xffffffffu, mx1, 2));
        float nm0 = fmaxf(mrow[0], mx0), nm1 = fmaxf(mrow[1], mx1);
        float al0 = fexp(mrow[0] - nm0),  al1 = fexp(mrow[1] - nm1);
        float s0 = 0.f, s1 = 0.f;
#pragma unroll
        for (int nt = 0; nt < 8; nt++) {
            float p0 = fexp(sacc[nt][0] - nm0);
            float p1 = fexp(sacc[nt][1] - nm0);
            float p2 = fexp(sacc[nt][2] - nm1);
            float p3 = fexp(sacc[nt][3] - nm1);
            s0 += p0 + p1;
            s1 += p2 + p3;
            *(__half2*)&ps[(m0 + grp    ) * ASTH + nt * 8 + 2 * tig] =
                __floats2half2_rn(p0, p1);
            *(__half2*)&ps[(m0 + grp + 8) * ASTH + nt * 8 + 2 * tig] =
                __floats2half2_rn(p2, p3);
        }
        s0 += __shfl_xor_sync(0xffffffffu, s0, 1);
        s0 += __shfl_xor_sync(0xffffffffu, s0, 2);
        s1 += __shfl_xor_sync(0xffffffffu, s1, 1);
        s1 += __shfl_xor_sync(0xffffffffu, s1, 2);
        lrow[0] = lrow[0] * al0 + s0;
        lrow[1] = lrow[1] * al1 + s1;
        mrow[0] = nm0; mrow[1] = nm1;
#pragma unroll
        for (int nt = 0; nt < 8; nt++) {
            oc[nt][0] *= al0; oc[nt][1] *= al0;
            oc[nt][2] *= al1; oc[nt][3] *= al1;
        }
        __syncwarp();

#pragma unroll
        for (int kk = 0; kk < 4; kk++) {
            const uint32_t* p0 = (const uint32_t*)&ps[(m0 + grp    ) * ASTH + kk * 16 + 2 * tig];
            const uint32_t* p1 = (const uint32_t*)&ps[(m0 + grp + 8) * ASTH + kk * 16 + 2 * tig];
            uint32_t pa0 = p0[0], pa1 = p1[0], pa2 = p0[4], pa3 = p1[4];
#pragma unroll
            for (int nt = 0; nt < 8; nt++) {
                const uint32_t* vr = (const uint32_t*)&vsT[(nt * 8 + grp) * ASTH + kk * 16 + 2 * tig];
                mma_f16(oc[nt], pa0, pa1, pa2, pa3, vr[0], vr[4]);
            }
        }
        __syncwarp();
    }

    float i0 = 1.0f / lrow[0], i1 = 1.0f / lrow[1];
    size_t tok0 = seq_base + qbase + m0 + grp;
#pragma unroll
    for (int nt = 0; nt < 8; nt++) {
        int col = h * DH + nt * 8 + 2 * tig;
        *(__half2*)&ctx[tok0 * INNER + col] =
            __floats2half2_rn(oc[nt][0] * i0, oc[nt][1] * i0);
        *(__half2*)&ctx[(tok0 + 8) * INNER + col] =
            __floats2half2_rn(oc[nt][2] * i1, oc[nt][3] * i1);
    }
}

// ---------------------------------------------------------------------------
// Host launch
// ---------------------------------------------------------------------------
extern "C" void kernel_launch(void* const* d_in, const int* in_sizes, int n_in,
                              void* d_out, int out_size)
{
    const float* x_in    = (const float*)d_in[0];
    const float* ln_s_g  = (const float*)d_in[1];
    const float* ln_s_b  = (const float*)d_in[2];
    const float* w_qkv_s = (const float*)d_in[3];
    const float* w_out_s = (const float*)d_in[4];
    const float* b_out_s = (const float*)d_in[5];
    const float* ln_t_g  = (const float*)d_in[6];
    const float* ln_t_b  = (const float*)d_in[7];
    const float* w_qkv_t = (const float*)d_in[8];
    const float* w_out_t = (const float*)d_in[9];
    const float* b_out_t = (const float*)d_in[10];
    const float* ln_f_g  = (const float*)d_in[11];
    const float* ln_f_b  = (const float*)d_in[12];
    float* x = (float*)d_out;

    cudaFuncSetAttribute(hgemm_kernel, cudaFuncAttributeMaxDynamicSharedMemorySize,
                         HGEMM_SMEM);

    __half *qkv_p, *ctx_p, *xs_p, *xt_p;
    uint32_t* wp_p;
    cudaGetSymbolAddress((void**)&qkv_p, g_qkv);
    cudaGetSymbolAddress((void**)&ctx_p, g_ctx);
    cudaGetSymbolAddress((void**)&xs_p,  g_xs);
    cudaGetSymbolAddress((void**)&xt_p,  g_xt);
    cudaGetSymbolAddress((void**)&wp_p,  g_wp);
    __half* ln_p = ctx_p;

    uint32_t* wp_qkv_s = wp_p;
    uint32_t* wp_out_s = wp_p + WQKV_SZ / 2;
    uint32_t* wp_qkv_t = wp_p + (WQKV_SZ + WOUT_SZ) / 2;
    uint32_t* wp_out_t = wp_p + WQKV_SZ + WOUT_SZ / 2;

    rope_table_kernel<<<(256 * 32 + 255) / 256, 256>>>();
    pack_all_kernel<<<dim3(((DD / 2) * QKV3 + 255) / 256, DEPTH, 4), 256>>>(
        w_qkv_s, w_out_s, w_qkv_t, w_out_t, wp_p);

    dim3 ln_grid(NTOK / 8);
    dim3 gemm_qkv_grid(NTOK / 128, QKV3 / 128);
    dim3 gemm_out_grid(NTOK / 128, DD / 128);
    dim3 attn_s_grid(PP / 128, HH, BB * TT);
    dim3 attn_t_grid(TT / 64, HH, BB * PP);

    // x <- input ; ln_p <- fp16(LN_s0(x))
    copy_ln_kernel<<<ln_grid, 256>>>(x_in, ln_s_g, ln_s_b, x, ln_p);

    for (int i = 0; i < DEPTH; i++) {
        const uint32_t* wq_s = wp_qkv_s + (size_t)i * (DD / 2) * QKV3;
        const uint32_t* wo_s = wp_out_s + (size_t)i * (INNER / 2) * DD;
        const uint32_t* wq_t = wp_qkv_t + (size_t)i * (DD / 2) * QKV3;
        const uint32_t* wo_t = wp_out_t + (size_t)i * (INNER / 2) * DD;

        // ---- spatial branch (ln_p already holds LN_s(x)) ----
        hgemm_kernel<<<gemm_qkv_grid, 256, HGEMM_SMEM>>>(ln_p, wq_s, nullptr, qkv_p,
                                                         NTOK, QKV3, DD);
        attn_tc_kernel<8><<<attn_s_grid, 256>>>(qkv_p, ctx_p, PP);
        hgemm_kernel<<<gemm_out_grid, 256, HGEMM_SMEM>>>(ctx_p, wo_s, b_out_s + i * DD, xs_p,
                                                         NTOK, DD, INNER);

        // ---- temporal branch ----
        ln_add_transpose_kernel<<<ln_grid, 256>>>(x, xs_p, ln_t_g + i * DD,
                                                  ln_t_b + i * DD, ln_p);
        hgemm_kernel<<<gemm_qkv_grid, 256, HGEMM_SMEM>>>(ln_p, wq_t, nullptr, qkv_p,
                                                         NTOK, QKV3, DD);
        attn_tc_kernel<4><<<attn_t_grid, 128>>>(qkv_p, ctx_p, TT);
        hgemm_kernel<<<gemm_out_grid, 256, HGEMM_SMEM>>>(ctx_p, wo_t, b_out_t + i * DD, xt_p,
                                                         NTOK, DD, INNER);

        // ---- finish: fold next layer's spatial pre-LN into the boundary ----
        if (i + 1 < DEPTH) {
            ln_final_fused_kernel<<<ln_grid, 256>>>(
                xs_p, xt_p, ln_f_g + i * DD, ln_f_b + i * DD,
                ln_s_g + (i + 1) * DD, ln_s_b + (i + 1) * DD, x, ln_p);
        } else {
            ln_final_kernel<<<ln_grid, 256>>>(xs_p, xt_p, ln_f_g + i * DD,
                                              ln_f_b + i * DD, x);
        }
    }
}